// round 16
// baseline (speedup 1.0000x reference)
#include <cuda_runtime.h>
#include <cuda_fp16.h>

#define N_NODES 100000
#define N_EDGES 1600000
#define F_IN 22
#define F_HID 32
#define CAP 96
#define MAX_SPILL 4096
#define NB 1036                  // 148 SMs * 7 blocks  (co-resident guaranteed)
#define NT 256

// ---------------- scratch (static device globals; no allocation) ----------
__device__ float g_M1[F_IN * F_HID];
__device__ float g_c1[F_HID];
__device__ float g_M2b[F_IN * F_HID];
__device__ float g_c2b[F_HID];
__device__ float g_Mp[F_IN];
__device__ float g_cp;
__device__ float g_dis[N_NODES];
__device__ int   g_slot[N_NODES];
__device__ int   g_is64;
__device__ int   g_spill_n;
__device__ int2  g_spill[MAX_SPILL];
__device__ __align__(16) int g_csr[(size_t)N_NODES * CAP];
__device__ __align__(16) __half g_p1h[(size_t)N_NODES * F_HID];
__device__ __align__(16) __half g_p2h[(size_t)N_NODES * F_HID];
__device__ __align__(16) __half g_q2h[(size_t)N_NODES * F_HID];
__device__ float g_q3[N_NODES];
__device__ unsigned int g_barr[4];   // generation-counted; NEVER reset

// ---------------- cg load helpers (L2-coherent cross-phase reads) ----------
__device__ __forceinline__ int ldcg_i(const int* p)
{ int v; asm volatile("ld.global.cg.b32 %0, [%1];" : "=r"(v) : "l"(p)); return v; }
__device__ __forceinline__ float ldcg_f(const float* p)
{ float v; asm volatile("ld.global.cg.f32 %0, [%1];" : "=f"(v) : "l"(p)); return v; }
__device__ __forceinline__ unsigned short ldcg_h(const __half* p)
{ unsigned short v; asm volatile("ld.global.cg.u16 %0, [%1];" : "=h"(v) : "l"(p)); return v; }
__device__ __forceinline__ int2 ldcg_i2(const int2* p)
{ int2 v; asm volatile("ld.global.cg.v2.b32 {%0,%1}, [%2];"
                       : "=r"(v.x), "=r"(v.y) : "l"(p)); return v; }

// Load 4 fp16 message features (8B) via L2 and widen to float4.
__device__ __forceinline__ float4 ldmsg_cg(const __half* p, int s, int l)
{
    unsigned int a, b;
    asm volatile("ld.global.cg.v2.b32 {%0,%1}, [%2];"
                 : "=r"(a), "=r"(b) : "l"(p + (size_t)s * F_HID + l * 4));
    float2 f0 = __half22float2(*reinterpret_cast<__half2*>(&a));
    float2 f1 = __half22float2(*reinterpret_cast<__half2*>(&b));
    return make_float4(f0.x, f0.y, f1.x, f1.y);
}

// ---------------- software grid barrier (generation-counted) ---------------
// Monotonic counter per barrier slot: works unchanged across graph replays.
__device__ __forceinline__ void grid_barrier(int idx)
{
    __syncthreads();
    if (threadIdx.x == 0) {
        __threadfence();                       // publish this block's writes
        unsigned int old = atomicAdd(&g_barr[idx], 1u);
        unsigned int target = (old / NB + 1u) * (unsigned int)NB;
        unsigned int cur;
        do {
            asm volatile("ld.global.cg.u32 %0, [%1];"
                         : "=r"(cur) : "l"(&g_barr[idx]) : "memory");
            if (cur < target) __nanosleep(64);
        } while (cur < target);
        __threadfence();
    }
    __syncthreads();
}

// ---------------- redistribute helper --------------------------------------
__device__ __forceinline__ float redist32(float4 acc, int lane)
{
    int srcl = lane >> 2;
    float fx = __shfl_sync(0xffffffffu, acc.x, srcl);
    float fy = __shfl_sync(0xffffffffu, acc.y, srcl);
    float fz = __shfl_sync(0xffffffffu, acc.z, srcl);
    float fw = __shfl_sync(0xffffffffu, acc.w, srcl);
    int c = lane & 3;
    return (c == 0) ? fx : (c == 1) ? fy : (c == 2) ? fz : fw;
}

// Gather core — R13 strided layout (best measured), cg loads.
__device__ __forceinline__ float gather_node(const __half* p, int n,
                                             int lane, int l, int g)
{
    int cnt = min(ldcg_i(&g_slot[n]), CAP);
    const int* row = g_csr + (size_t)n * CAP;
    float4 acc;
    if (g == 0) acc = ldmsg_cg(p, n, l);
    else        acc = make_float4(0.f, 0.f, 0.f, 0.f);
    int e = g;
    for (; e + 12 < cnt; e += 16) {
        int s0 = ldcg_i(row + e);
        int s1 = ldcg_i(row + e + 4);
        int s2 = ldcg_i(row + e + 8);
        int s3 = ldcg_i(row + e + 12);
        float4 v0 = ldmsg_cg(p, s0, l);
        float4 v1 = ldmsg_cg(p, s1, l);
        float4 v2 = ldmsg_cg(p, s2, l);
        float4 v3 = ldmsg_cg(p, s3, l);
        acc.x += (v0.x + v1.x) + (v2.x + v3.x);
        acc.y += (v0.y + v1.y) + (v2.y + v3.y);
        acc.z += (v0.z + v1.z) + (v2.z + v3.z);
        acc.w += (v0.w + v1.w) + (v2.w + v3.w);
    }
    for (; e < cnt; e += 4) {
        float4 v = ldmsg_cg(p, ldcg_i(row + e), l);
        acc.x += v.x; acc.y += v.y; acc.z += v.z; acc.w += v.w;
    }
    int nsp = ldcg_i(&g_spill_n);
    if (nsp > 0) {
        if (nsp > MAX_SPILL) nsp = MAX_SPILL;
        for (int i = g; i < nsp; i += 4) {
            int2 ed = ldcg_i2(&g_spill[i]);
            if (ed.x == n) {
                float4 v = ldmsg_cg(p, ed.y, l);
                acc.x += v.x; acc.y += v.y; acc.z += v.z; acc.w += v.w;
            }
        }
    }
    #pragma unroll
    for (int off = 8; off <= 16; off <<= 1) {
        acc.x += __shfl_xor_sync(0xffffffffu, acc.x, off);
        acc.y += __shfl_xor_sync(0xffffffffu, acc.y, off);
        acc.z += __shfl_xor_sync(0xffffffffu, acc.z, off);
        acc.w += __shfl_xor_sync(0xffffffffu, acc.w, off);
    }
    return redist32(acc, lane);
}

// ---------------- the single persistent kernel ------------------------------
__global__ void __launch_bounds__(NT, 7) k_mega(
    const void*  __restrict__ ei,
    const float* __restrict__ x,
    const float* __restrict__ We, const float* __restrict__ be,
    const float* __restrict__ W1, const float* __restrict__ b1,
    const float* __restrict__ W2, const float* __restrict__ b2,
    const float* __restrict__ Wp, const float* __restrict__ bp,
    float* __restrict__ out)
{
    __shared__ float sBuf[1536];      // union across phases (6 KB)
    __shared__ int   s_flag;

    int t    = threadIdx.x;
    int bid  = blockIdx.x;
    int lane = t & 31;
    int warp = (bid * NT + t) >> 5;
    const int nwarp = (NB * NT) >> 5;

    // ================= P0: zero g_slot + sniff + weight fusion =============
    {
        int i = bid * NT + t;
        if (i < N_NODES) g_slot[i] = 0;        // NB*NT > N_NODES: single pass
        if (bid == 0) {
            const long long* p64 = (const long long*)ei;
            long long v = p64[(long long)t * (N_EDGES / 256)];
            int ok = (v >= 0 && v < N_NODES) ? 1 : 0;
            if (t == 0) { s_flag = 1; g_spill_n = 0; }
            __syncthreads();
            if (!ok) atomicAnd(&s_flag, 0);
            __syncthreads();
            if (t == 0) g_is64 = s_flag;
        }
        if (bid == 1) {
            for (int q = t; q < F_IN * F_HID; q += NT) {
                int k = q / F_HID, j = q % F_HID;
                float m1 = 0.f, m2b = 0.f;
                for (int u = 0; u < F_HID; ++u) {
                    float we = We[k * F_HID + u];
                    m1  += we * W1[u * F_HID + j];
                    m2b += we * W2[(F_HID + u) * F_HID + j];
                }
                g_M1[q]  = m1;
                g_M2b[q] = m2b;
            }
            if (t < F_HID) {
                float c1 = 0.f, c2b = 0.f;
                for (int u = 0; u < F_HID; ++u) {
                    c1  += be[u] * W1[u * F_HID + t];
                    c2b += be[u] * W2[(F_HID + u) * F_HID + t];
                }
                g_c1[t]  = c1;
                g_c2b[t] = c2b;
            }
            if (t >= 64 && t < 64 + F_IN) {
                int k = t - 64;
                float mp = 0.f;
                for (int u = 0; u < F_HID; ++u)
                    mp += We[k * F_HID + u] * Wp[F_HID + u];
                g_Mp[k] = mp;
            }
            if (t == 255) {
                float cp = 0.f;
                for (int u = 0; u < F_HID; ++u) cp += be[u] * Wp[F_HID + u];
                g_cp = cp;
            }
        }
    }
    grid_barrier(0);

    // ================= P1: bucket placement =================================
    {
        int is64 = ldcg_i(&g_is64);
        int stride = NB * NT;
        if (is64) {
            const long long* ps = (const long long*)ei;
            const long long* pd = ps + N_EDGES;
            for (int e = bid * NT + t; e < N_EDGES; e += stride) {
                int s = (int)ps[e], d = (int)pd[e];
                int slot = atomicAdd(&g_slot[d], 1);
                if (slot < CAP) g_csr[(size_t)d * CAP + slot] = s;
                else {
                    int sp = atomicAdd(&g_spill_n, 1);
                    if (sp < MAX_SPILL) g_spill[sp] = make_int2(d, s);
                }
            }
        } else {
            const int* ps = (const int*)ei;
            const int* pd = ps + N_EDGES;
            for (int e = bid * NT + t; e < N_EDGES; e += stride) {
                int s = ps[e], d = pd[e];
                int slot = atomicAdd(&g_slot[d], 1);
                if (slot < CAP) g_csr[(size_t)d * CAP + slot] = s;
                else {
                    int sp = atomicAdd(&g_spill_n, 1);
                    if (sp < MAX_SPILL) g_spill[sp] = make_int2(d, s);
                }
            }
        }
    }
    grid_barrier(1);

    // ================= P2: node1 (p1, q2, q3, dis) ==========================
    {
        float* sM1  = sBuf;            // 704
        float* sM2b = sBuf + 704;      // 704
        float* sc1  = sBuf + 1408;     // 32
        float* sc2b = sBuf + 1440;     // 32
        float* sMp  = sBuf + 1472;     // 22
        for (int i = t; i < F_IN * F_HID; i += NT) {
            sM1[i]  = ldcg_f(&g_M1[i]);
            sM2b[i] = ldcg_f(&g_M2b[i]);
        }
        if (t < F_HID) { sc1[t]  = ldcg_f(&g_c1[t]);
                         sc2b[t] = ldcg_f(&g_c2b[t]); }
        if (t < F_IN) sMp[t] = ldcg_f(&g_Mp[t]);
        __syncthreads();
        float cp = ldcg_f(&g_cp);

        for (int n = warp; n < N_NODES; n += nwarp) {
            float dis = rsqrtf((float)(ldcg_i(&g_slot[n]) + 1));
            if (lane == 0) g_dis[n] = dis;
            const float* xr = x + (size_t)n * F_IN;
            float acc1 = sc1[lane];
            float acc2 = sc2b[lane];
            float xv   = (lane < F_IN) ? xr[lane] : 0.f;
            #pragma unroll
            for (int k = 0; k < F_IN; ++k) {
                float xk = __shfl_sync(0xffffffffu, xv, k);
                acc1 += xk * sM1[k * F_HID + lane];
                acc2 += xk * sM2b[k * F_HID + lane];
            }
            size_t o = (size_t)n * F_HID + lane;
            g_p1h[o] = __float2half(dis * acc1);
            g_q2h[o] = __float2half(acc2);
            float part = (lane < F_IN) ? xv * sMp[lane] : 0.f;
            #pragma unroll
            for (int off = 16; off; off >>= 1)
                part += __shfl_xor_sync(0xffffffffu, part, off);
            float x1 = __shfl_sync(0xffffffffu, xv, 1);
            if (lane == 0) g_q3[n] = part + cp + x1;
        }
    }
    grid_barrier(2);

    // ================= P3: gather1 + node2 ==================================
    {
        float* sW2t = sBuf;            // 1024
        float* sb1  = sBuf + 1024;     // 32
        for (int i = t; i < F_HID * F_HID; i += NT) sW2t[i] = W2[i];
        if (t < F_HID) sb1[t] = b1[t];
        __syncthreads();

        int l = lane & 7, g = lane >> 3;
        float b1l = sb1[lane];
        for (int n = warp; n < N_NODES; n += nwarp) {
            float a1j = gather_node(g_p1h, n, lane, l, g);
            float dis = ldcg_f(&g_dis[n]);
            float r1  = fmaxf(dis * a1j + b1l, 0.f);
            size_t o = (size_t)n * F_HID + lane;
            float acc = __half2float(__ushort_as_half(ldcg_h(&g_q2h[o])));
            #pragma unroll
            for (int k = 0; k < F_HID; ++k) {
                float rk = __shfl_sync(0xffffffffu, r1, k);
                acc += rk * sW2t[k * F_HID + lane];
            }
            g_p2h[o] = __float2half(dis * acc);
        }
    }
    grid_barrier(3);

    // ================= P4: gather2 + prediction =============================
    {
        int l = lane & 7, g = lane >> 3;
        float b2l = b2[lane];
        float wpl = Wp[lane];
        float bp0 = bp[0];
        for (int n = warp; n < N_NODES; n += nwarp) {
            float a2j = gather_node(g_p2h, n, lane, l, g);
            float dis = ldcg_f(&g_dis[n]);
            float r2  = fmaxf(dis * a2j + b2l, 0.f);
            float part = r2 * wpl;
            #pragma unroll
            for (int off = 16; off; off >>= 1)
                part += __shfl_xor_sync(0xffffffffu, part, off);
            if (lane == 0)
                out[n] = fmaxf(part + ldcg_f(&g_q3[n]) + bp0, 0.f);
        }
    }
}

// ---------------- launch ----------------------------------------------------
extern "C" void kernel_launch(void* const* d_in, const int* in_sizes, int n_in,
                              void* d_out, int out_size)
{
    const float* x   = (const float*)d_in[0];
    const void*  ei  = d_in[1];
    const float* We  = (const float*)d_in[2];
    const float* be  = (const float*)d_in[3];
    const float* W1  = (const float*)d_in[4];
    const float* b1  = (const float*)d_in[5];
    const float* W2  = (const float*)d_in[6];
    const float* b2  = (const float*)d_in[7];
    const float* Wp  = (const float*)d_in[8];
    const float* bp  = (const float*)d_in[9];
    float*       out = (float*)d_out;

    k_mega<<<NB, NT>>>(ei, x, We, be, W1, b1, W2, b2, Wp, bp, out);
}

// round 17
// speedup vs baseline: 1.0389x; 1.0389x over previous
#include <cuda_runtime.h>
#include <cuda_fp16.h>

#define N_NODES 100000
#define N_EDGES 1600000
#define F_IN 22
#define F_HID 32
#define CAP 96
#define MAX_SPILL 4096
#define NB 1036                  // 148 SMs * 7 blocks  (co-resident guaranteed)
#define NT 256

// ---------------- scratch (static device globals; no allocation) ----------
__device__ float g_M1[F_IN * F_HID];
__device__ float g_c1[F_HID];
__device__ float g_M2b[F_IN * F_HID];
__device__ float g_c2b[F_HID];
__device__ float g_Mp[F_IN];
__device__ float g_cp;
__device__ float g_dis[N_NODES];
__device__ int   g_slot[N_NODES];
__device__ int   g_is64;
__device__ int   g_spill_n;
__device__ int2  g_spill[MAX_SPILL];
__device__ __align__(16) int g_csr[(size_t)N_NODES * CAP];
__device__ __align__(16) __half g_p1h[(size_t)N_NODES * F_HID];
__device__ __align__(16) __half g_p2h[(size_t)N_NODES * F_HID];
__device__ __align__(16) __half g_q2h[(size_t)N_NODES * F_HID];
__device__ float g_q3[N_NODES];
__device__ unsigned int g_barr[4];   // generation-counted; NEVER reset

// ---------------- software grid barrier (generation-counted) ---------------
// Only the barrier word itself needs L1-bypass loads; all data buffers obey
// write-phase < read-phase (no read-before-remote-write), so default .ca
// loads are coherent given write-through L1 + per-launch L1 flush.
__device__ __forceinline__ void grid_barrier(int idx)
{
    __syncthreads();
    if (threadIdx.x == 0) {
        __threadfence();                       // publish this block's writes
        unsigned int old = atomicAdd(&g_barr[idx], 1u);
        unsigned int target = (old / NB + 1u) * (unsigned int)NB;
        unsigned int cur;
        do {
            asm volatile("ld.global.cg.u32 %0, [%1];"
                         : "=r"(cur) : "l"(&g_barr[idx]) : "memory");
            if (cur < target) __nanosleep(64);
        } while (cur < target);
        __threadfence();
    }
    __syncthreads();
}

// ---------------- helpers ----------------------------------------------------
// Load 4 fp16 message features (one 8B uint2) and widen to float4.
__device__ __forceinline__ float4 ldmsg(const __half* __restrict__ p, int s, int l)
{
    uint2 v = *reinterpret_cast<const uint2*>(p + (size_t)s * F_HID + l * 4);
    float2 f0 = __half22float2(*reinterpret_cast<const __half2*>(&v.x));
    float2 f1 = __half22float2(*reinterpret_cast<const __half2*>(&v.y));
    return make_float4(f0.x, f0.y, f1.x, f1.y);
}

__device__ __forceinline__ float redist32(float4 acc, int lane)
{
    int srcl = lane >> 2;
    float fx = __shfl_sync(0xffffffffu, acc.x, srcl);
    float fy = __shfl_sync(0xffffffffu, acc.y, srcl);
    float fz = __shfl_sync(0xffffffffu, acc.z, srcl);
    float fw = __shfl_sync(0xffffffffu, acc.w, srcl);
    int c = lane & 3;
    return (c == 0) ? fx : (c == 1) ? fy : (c == 2) ? fz : fw;
}

// Gather core — R13 strided layout (best measured), default cached loads.
__device__ __forceinline__ float gather_node(const __half* __restrict__ p, int n,
                                             int lane, int l, int g)
{
    int cnt = min(g_slot[n], CAP);
    const int* row = g_csr + (size_t)n * CAP;
    float4 acc;
    if (g == 0) acc = ldmsg(p, n, l);
    else        acc = make_float4(0.f, 0.f, 0.f, 0.f);
    int e = g;
    for (; e + 12 < cnt; e += 16) {
        int s0 = row[e];
        int s1 = row[e + 4];
        int s2 = row[e + 8];
        int s3 = row[e + 12];
        float4 v0 = ldmsg(p, s0, l);
        float4 v1 = ldmsg(p, s1, l);
        float4 v2 = ldmsg(p, s2, l);
        float4 v3 = ldmsg(p, s3, l);
        acc.x += (v0.x + v1.x) + (v2.x + v3.x);
        acc.y += (v0.y + v1.y) + (v2.y + v3.y);
        acc.z += (v0.z + v1.z) + (v2.z + v3.z);
        acc.w += (v0.w + v1.w) + (v2.w + v3.w);
    }
    for (; e < cnt; e += 4) {
        float4 v = ldmsg(p, row[e], l);
        acc.x += v.x; acc.y += v.y; acc.z += v.z; acc.w += v.w;
    }
    int nsp = g_spill_n;
    if (nsp > 0) {
        if (nsp > MAX_SPILL) nsp = MAX_SPILL;
        for (int i = g; i < nsp; i += 4) {
            int2 ed = g_spill[i];
            if (ed.x == n) {
                float4 v = ldmsg(p, ed.y, l);
                acc.x += v.x; acc.y += v.y; acc.z += v.z; acc.w += v.w;
            }
        }
    }
    #pragma unroll
    for (int off = 8; off <= 16; off <<= 1) {
        acc.x += __shfl_xor_sync(0xffffffffu, acc.x, off);
        acc.y += __shfl_xor_sync(0xffffffffu, acc.y, off);
        acc.z += __shfl_xor_sync(0xffffffffu, acc.z, off);
        acc.w += __shfl_xor_sync(0xffffffffu, acc.w, off);
    }
    return redist32(acc, lane);
}

// ---------------- the single persistent kernel ------------------------------
__global__ void __launch_bounds__(NT, 7) k_mega(
    const void*  __restrict__ ei,
    const float* __restrict__ x,
    const float* __restrict__ We, const float* __restrict__ be,
    const float* __restrict__ W1, const float* __restrict__ b1,
    const float* __restrict__ W2, const float* __restrict__ b2,
    const float* __restrict__ Wp, const float* __restrict__ bp,
    float* __restrict__ out)
{
    __shared__ float sBuf[1536];      // union across phases (6 KB)
    __shared__ int   s_flag;

    int t    = threadIdx.x;
    int bid  = blockIdx.x;
    int lane = t & 31;
    int warp = (bid * NT + t) >> 5;
    const int nwarp = (NB * NT) >> 5;

    // ================= P0: zero g_slot + sniff + weight fusion =============
    {
        int i = bid * NT + t;
        if (i < N_NODES) g_slot[i] = 0;        // NB*NT > N_NODES: single pass
        if (bid == 0) {
            const long long* p64 = (const long long*)ei;
            long long v = p64[(long long)t * (N_EDGES / 256)];
            int ok = (v >= 0 && v < N_NODES) ? 1 : 0;
            if (t == 0) { s_flag = 1; g_spill_n = 0; }
            __syncthreads();
            if (!ok) atomicAnd(&s_flag, 0);
            __syncthreads();
            if (t == 0) g_is64 = s_flag;
        }
        if (bid == 1) {
            for (int q = t; q < F_IN * F_HID; q += NT) {
                int k = q / F_HID, j = q % F_HID;
                float m1 = 0.f, m2b = 0.f;
                for (int u = 0; u < F_HID; ++u) {
                    float we = We[k * F_HID + u];
                    m1  += we * W1[u * F_HID + j];
                    m2b += we * W2[(F_HID + u) * F_HID + j];
                }
                g_M1[q]  = m1;
                g_M2b[q] = m2b;
            }
            if (t < F_HID) {
                float c1 = 0.f, c2b = 0.f;
                for (int u = 0; u < F_HID; ++u) {
                    c1  += be[u] * W1[u * F_HID + t];
                    c2b += be[u] * W2[(F_HID + u) * F_HID + t];
                }
                g_c1[t]  = c1;
                g_c2b[t] = c2b;
            }
            if (t >= 64 && t < 64 + F_IN) {
                int k = t - 64;
                float mp = 0.f;
                for (int u = 0; u < F_HID; ++u)
                    mp += We[k * F_HID + u] * Wp[F_HID + u];
                g_Mp[k] = mp;
            }
            if (t == 255) {
                float cp = 0.f;
                for (int u = 0; u < F_HID; ++u) cp += be[u] * Wp[F_HID + u];
                g_cp = cp;
            }
        }
    }
    grid_barrier(0);

    // ================= P1: bucket placement =================================
    {
        int is64 = g_is64;
        int stride = NB * NT;
        if (is64) {
            const long long* ps = (const long long*)ei;
            const long long* pd = ps + N_EDGES;
            for (int e = bid * NT + t; e < N_EDGES; e += stride) {
                int s = (int)ps[e], d = (int)pd[e];
                int slot = atomicAdd(&g_slot[d], 1);
                if (slot < CAP) g_csr[(size_t)d * CAP + slot] = s;
                else {
                    int sp = atomicAdd(&g_spill_n, 1);
                    if (sp < MAX_SPILL) g_spill[sp] = make_int2(d, s);
                }
            }
        } else {
            const int* ps = (const int*)ei;
            const int* pd = ps + N_EDGES;
            for (int e = bid * NT + t; e < N_EDGES; e += stride) {
                int s = ps[e], d = pd[e];
                int slot = atomicAdd(&g_slot[d], 1);
                if (slot < CAP) g_csr[(size_t)d * CAP + slot] = s;
                else {
                    int sp = atomicAdd(&g_spill_n, 1);
                    if (sp < MAX_SPILL) g_spill[sp] = make_int2(d, s);
                }
            }
        }
    }
    grid_barrier(1);

    // ================= P2: node1 (p1, q2, q3, dis) ==========================
    {
        float* sM1  = sBuf;            // 704
        float* sM2b = sBuf + 704;      // 704
        float* sc1  = sBuf + 1408;     // 32
        float* sc2b = sBuf + 1440;     // 32
        float* sMp  = sBuf + 1472;     // 22
        for (int i = t; i < F_IN * F_HID; i += NT) {
            sM1[i]  = g_M1[i];
            sM2b[i] = g_M2b[i];
        }
        if (t < F_HID) { sc1[t]  = g_c1[t];
                         sc2b[t] = g_c2b[t]; }
        if (t < F_IN) sMp[t] = g_Mp[t];
        __syncthreads();
        float cp = g_cp;

        for (int n = warp; n < N_NODES; n += nwarp) {
            float dis = rsqrtf((float)(g_slot[n] + 1));
            if (lane == 0) g_dis[n] = dis;
            const float* xr = x + (size_t)n * F_IN;
            float acc1 = sc1[lane];
            float acc2 = sc2b[lane];
            float xv   = (lane < F_IN) ? xr[lane] : 0.f;
            #pragma unroll
            for (int k = 0; k < F_IN; ++k) {
                float xk = __shfl_sync(0xffffffffu, xv, k);
                acc1 += xk * sM1[k * F_HID + lane];
                acc2 += xk * sM2b[k * F_HID + lane];
            }
            size_t o = (size_t)n * F_HID + lane;
            g_p1h[o] = __float2half(dis * acc1);
            g_q2h[o] = __float2half(acc2);
            float part = (lane < F_IN) ? xv * sMp[lane] : 0.f;
            #pragma unroll
            for (int off = 16; off; off >>= 1)
                part += __shfl_xor_sync(0xffffffffu, part, off);
            float x1 = __shfl_sync(0xffffffffu, xv, 1);
            if (lane == 0) g_q3[n] = part + cp + x1;
        }
    }
    grid_barrier(2);

    // ================= P3: gather1 + node2 ==================================
    {
        float* sW2t = sBuf;            // 1024
        float* sb1  = sBuf + 1024;     // 32
        for (int i = t; i < F_HID * F_HID; i += NT) sW2t[i] = W2[i];
        if (t < F_HID) sb1[t] = b1[t];
        __syncthreads();

        int l = lane & 7, g = lane >> 3;
        float b1l = sb1[lane];
        for (int n = warp; n < N_NODES; n += nwarp) {
            float a1j = gather_node(g_p1h, n, lane, l, g);
            float dis = g_dis[n];
            float r1  = fmaxf(dis * a1j + b1l, 0.f);
            size_t o = (size_t)n * F_HID + lane;
            float acc = __half2float(g_q2h[o]);
            #pragma unroll
            for (int k = 0; k < F_HID; ++k) {
                float rk = __shfl_sync(0xffffffffu, r1, k);
                acc += rk * sW2t[k * F_HID + lane];
            }
            g_p2h[o] = __float2half(dis * acc);
        }
    }
    grid_barrier(3);

    // ================= P4: gather2 + prediction =============================
    {
        int l = lane & 7, g = lane >> 3;
        float b2l = b2[lane];
        float wpl = Wp[lane];
        float bp0 = bp[0];
        for (int n = warp; n < N_NODES; n += nwarp) {
            float a2j = gather_node(g_p2h, n, lane, l, g);
            float dis = g_dis[n];
            float r2  = fmaxf(dis * a2j + b2l, 0.f);
            float part = r2 * wpl;
            #pragma unroll
            for (int off = 16; off; off >>= 1)
                part += __shfl_xor_sync(0xffffffffu, part, off);
            if (lane == 0)
                out[n] = fmaxf(part + g_q3[n] + bp0, 0.f);
        }
    }
}

// ---------------- launch ----------------------------------------------------
extern "C" void kernel_launch(void* const* d_in, const int* in_sizes, int n_in,
                              void* d_out, int out_size)
{
    const float* x   = (const float*)d_in[0];
    const void*  ei  = d_in[1];
    const float* We  = (const float*)d_in[2];
    const float* be  = (const float*)d_in[3];
    const float* W1  = (const float*)d_in[4];
    const float* b1  = (const float*)d_in[5];
    const float* W2  = (const float*)d_in[6];
    const float* b2  = (const float*)d_in[7];
    const float* Wp  = (const float*)d_in[8];
    const float* bp  = (const float*)d_in[9];
    float*       out = (float*)d_out;

    k_mega<<<NB, NT>>>(ei, x, We, be, W1, b1, W2, b2, Wp, bp, out);
}